// round 1
// baseline (speedup 1.0000x reference)
#include <cuda_runtime.h>
#include <math.h>

// Problem constants
#define B_  64
#define T_  4096
#define D_  512
#define S_  16                     // segments per batch
#define ROWS_PER_SEG (T_ / S_)     // 256
#define CHUNK 16                   // rows per chunk (== #warps)
#define NCHUNK (ROWS_PER_SEG / CHUNK)  // 16
#define THREADS 512

// Scratch for per-(batch,segment) partial online-softmax state.
__device__ float g_part_m[B_ * S_];
__device__ float g_part_l[B_ * S_];
__device__ float g_part_acc[B_ * S_ * D_];

__device__ __forceinline__ float neg_inf() { return __int_as_float(0xff800000); }

// -----------------------------------------------------------------------------
// Pass 1: fused GEMV + online softmax + weighted accumulation, one segment per
// CTA. Reads each element of x exactly once from HBM. Raw energies are written
// into the weights region of d_out (normalized in pass 2).
// -----------------------------------------------------------------------------
__global__ __launch_bounds__(THREADS, 2)
void attn_pass1(const float* __restrict__ x,
                const float* __restrict__ v,
                float* __restrict__ energies_out)   // d_out + B*D, raw energies
{
    __shared__ float sv[D_];        // attention vector
    __shared__ float se[CHUNK];     // chunk energies
    __shared__ float sp[CHUNK];     // chunk probabilities exp(e - m_new)
    __shared__ float sscale;        // rescale factor exp(m_old - m_new)

    const int tid  = threadIdx.x;
    const int warp = tid >> 5;
    const int lane = tid & 31;
    const int b    = blockIdx.x / S_;
    const int s    = blockIdx.x % S_;
    const int t0   = s * ROWS_PER_SEG;

    const float* xb = x + ((size_t)b * T_ + t0) * D_;

    for (int i = tid; i < D_; i += THREADS) sv[i] = v[i];
    __syncthreads();

    float m = neg_inf();     // meaningful only in warp 0
    float l = 0.f;           // meaningful only in warp 0
    float4 acc = make_float4(0.f, 0.f, 0.f, 0.f);  // threads 0..127 own col4=tid

    for (int c = 0; c < NCHUNK; c++) {
        // ---- Phase A: warp w computes energy of row (c*16 + w) -------------
        {
            const int r = c * CHUNK + warp;
            const float4* xr = reinterpret_cast<const float4*>(xb + (size_t)r * D_);
            const float4* vv = reinterpret_cast<const float4*>(sv);
            float e = 0.f;
            #pragma unroll
            for (int k = 0; k < 4; k++) {
                float4 xv = xr[lane + 32 * k];   // 512B coalesced per warp
                float4 vw = vv[lane + 32 * k];
                e += xv.x * vw.x + xv.y * vw.y + xv.z * vw.z + xv.w * vw.w;
            }
            #pragma unroll
            for (int o = 16; o; o >>= 1)
                e += __shfl_xor_sync(0xffffffffu, e, o);
            if (lane == 0) {
                se[warp] = e;
                energies_out[(size_t)b * T_ + t0 + r] = e;  // raw energy
            }
        }
        __syncthreads();

        // ---- Warp 0: online-softmax bookkeeping (keeps MUFU work tiny) -----
        if (warp == 0) {
            float ei = (lane < CHUNK) ? se[lane] : neg_inf();
            float cm = ei;
            #pragma unroll
            for (int o = 16; o; o >>= 1)
                cm = fmaxf(cm, __shfl_xor_sync(0xffffffffu, cm, o));
            float nm = fmaxf(m, cm);
            float sc = __expf(m - nm);           // exp(-inf)=0 on first chunk
            float p  = (lane < CHUNK) ? __expf(ei - nm) : 0.f;
            float ps = p;
            #pragma unroll
            for (int o = 16; o; o >>= 1)
                ps += __shfl_xor_sync(0xffffffffu, ps, o);
            l = l * sc + ps;
            m = nm;
            if (lane < CHUNK) sp[lane] = p;
            if (lane == 0)    sscale   = sc;
        }
        __syncthreads();

        // ---- Phase B: 4 warps re-read chunk from L1, update accumulators ---
        if (tid < D_ / 4) {
            float sc = sscale;
            acc.x *= sc; acc.y *= sc; acc.z *= sc; acc.w *= sc;
            #pragma unroll
            for (int i = 0; i < CHUNK; i++) {
                float p = sp[i];   // smem broadcast — conflict-free
                float4 xv = reinterpret_cast<const float4*>(
                                xb + (size_t)(c * CHUNK + i) * D_)[tid];
                acc.x += p * xv.x; acc.y += p * xv.y;
                acc.z += p * xv.z; acc.w += p * xv.w;
            }
        }
        // No trailing barrier needed: next iteration's se writes happen only
        // after its own __syncthreads() following Phase A, and Phase A never
        // touches sp/sscale.
        __syncthreads();
    }

    const int bs = b * S_ + s;
    if (warp == 0 && lane == 0) {
        g_part_m[bs] = m;
        g_part_l[bs] = l;
    }
    if (tid < D_ / 4) {
        reinterpret_cast<float4*>(g_part_acc + (size_t)bs * D_)[tid] = acc;
    }
}

// -----------------------------------------------------------------------------
// Pass 2: one CTA per batch. Merge segment partials, write context, and
// normalize raw energies into softmax weights in place.
// -----------------------------------------------------------------------------
__global__ __launch_bounds__(THREADS)
void attn_pass2(float* __restrict__ context,   // d_out            [B*D]
                float* __restrict__ weights)   // d_out + B*D      [B*T], holds raw energies
{
    __shared__ float sm_[S_];
    __shared__ float sl_[S_];

    const int b   = blockIdx.x;
    const int tid = threadIdx.x;

    if (tid < S_) {
        sm_[tid] = g_part_m[b * S_ + tid];
        sl_[tid] = g_part_l[b * S_ + tid];
    }
    __syncthreads();

    // Redundant tiny reduction in every thread (S_=16).
    float M = neg_inf();
    #pragma unroll
    for (int si = 0; si < S_; si++) M = fmaxf(M, sm_[si]);
    float L = 0.f;
    #pragma unroll
    for (int si = 0; si < S_; si++) L += sl_[si] * __expf(sm_[si] - M);
    const float invL = 1.f / L;

    // context[b, tid]
    {
        float a = 0.f;
        #pragma unroll
        for (int si = 0; si < S_; si++) {
            a += g_part_acc[(size_t)(b * S_ + si) * D_ + tid] * __expf(sm_[si] - M);
        }
        context[(size_t)b * D_ + tid] = a * invL;
    }

    // weights[b, t] = exp(e - M) / L   (in place over raw energies)
    for (int t = tid; t < T_; t += THREADS) {
        float e = weights[(size_t)b * T_ + t];
        weights[(size_t)b * T_ + t] = __expf(e - M) * invL;
    }
}

// -----------------------------------------------------------------------------
extern "C" void kernel_launch(void* const* d_in, const int* in_sizes, int n_in,
                              void* d_out, int out_size)
{
    const float* x = (const float*)d_in[0];   // encoder_outputs [B,T,D]
    const float* v = (const float*)d_in[1];   // attn_weights_param [D,1]
    float* out = (float*)d_out;
    float* ctx = out;                 // [B*D]
    float* wts = out + B_ * D_;       // [B*T]

    attn_pass1<<<B_ * S_, THREADS>>>(x, v, wts);
    attn_pass2<<<B_, THREADS>>>(ctx, wts);
}

// round 2
// speedup vs baseline: 1.2913x; 1.2913x over previous
#include <cuda_runtime.h>
#include <math.h>

// Problem constants
#define B_  64
#define T_  4096
#define D_  512
#define S_  16                     // segments per batch
#define ROWS_PER_SEG (T_ / S_)     // 256
#define CHUNK 16                   // rows per chunk (== #warps)
#define NCHUNK (ROWS_PER_SEG / CHUNK)  // 16
#define THREADS 512

#define THREADS2 256
#define SPLIT2   16                // pass2 blocks per batch

// Scratch for per-(batch,segment) partial online-softmax state.
__device__ float g_part_m[B_ * S_];
__device__ float g_part_l[B_ * S_];
__device__ float g_part_acc[B_ * S_ * D_];

__device__ __forceinline__ float neg_inf() { return __int_as_float(0xff800000); }

// -----------------------------------------------------------------------------
// Pass 1: fused GEMV + online softmax + weighted accumulation.
// One segment per CTA; 16 warps; each warp processes one row per chunk and
// keeps a PRIVATE register accumulator. One __syncthreads per chunk (energy
// exchange, double-buffered). All warps redundantly track (m) — identical by
// induction — so there is no serialized bookkeeping warp and no L1 re-read.
// -----------------------------------------------------------------------------
__global__ __launch_bounds__(THREADS, 2)
void attn_pass1(const float* __restrict__ x,
                const float* __restrict__ v,
                float* __restrict__ energies_out)   // raw energies -> weights region
{
    __shared__ float sv[D_];            // attention vector
    __shared__ float se[2][CHUNK];      // chunk energies, double-buffered
    __shared__ float sl[CHUNK];         // per-warp l partials (epilogue)
    __shared__ float4 sacc4[CHUNK * (D_ / 4)];  // 32KB cross-warp reduce buffer

    const int tid  = threadIdx.x;
    const int warp = tid >> 5;
    const int lane = tid & 31;
    const int b    = blockIdx.x / S_;
    const int s    = blockIdx.x % S_;
    const int t0   = s * ROWS_PER_SEG;

    const float*  xb  = x + ((size_t)b * T_ + t0) * D_;
    const float4* vv  = reinterpret_cast<const float4*>(sv);

    for (int i = tid; i < D_; i += THREADS) sv[i] = v[i];
    __syncthreads();

    // v values this lane dots against (lane-private, loop-invariant)
    float4 vw0 = vv[lane +  0];
    float4 vw1 = vv[lane + 32];
    float4 vw2 = vv[lane + 64];
    float4 vw3 = vv[lane + 96];

    float m = neg_inf();
    float l = 0.f;
    float4 acc0 = make_float4(0.f,0.f,0.f,0.f);
    float4 acc1 = make_float4(0.f,0.f,0.f,0.f);
    float4 acc2 = make_float4(0.f,0.f,0.f,0.f);
    float4 acc3 = make_float4(0.f,0.f,0.f,0.f);

    for (int c = 0; c < NCHUNK; c++) {
        const int buf = c & 1;
        const int r   = c * CHUNK + warp;
        const float4* xr = reinterpret_cast<const float4*>(xb + (size_t)r * D_);

        // ---- load row (4 independent 16B loads per lane) and dot with v ----
        float4 x0 = xr[lane +  0];
        float4 x1 = xr[lane + 32];
        float4 x2 = xr[lane + 64];
        float4 x3 = xr[lane + 96];

        float e = x0.x*vw0.x + x0.y*vw0.y + x0.z*vw0.z + x0.w*vw0.w
                + x1.x*vw1.x + x1.y*vw1.y + x1.z*vw1.z + x1.w*vw1.w
                + x2.x*vw2.x + x2.y*vw2.y + x2.z*vw2.z + x2.w*vw2.w
                + x3.x*vw3.x + x3.y*vw3.y + x3.z*vw3.z + x3.w*vw3.w;
        #pragma unroll
        for (int o = 16; o; o >>= 1)
            e += __shfl_xor_sync(0xffffffffu, e, o);   // all lanes hold e

        if (lane == 0) {
            se[buf][warp] = e;
            energies_out[(size_t)b * T_ + t0 + r] = e;
        }
        __syncthreads();   // single barrier per chunk

        // ---- every warp redundantly computes chunk max / rescale -----------
        float cm = (lane < CHUNK) ? se[buf][lane] : neg_inf();
        #pragma unroll
        for (int o = 16; o; o >>= 1)
            cm = fmaxf(cm, __shfl_xor_sync(0xffffffffu, cm, o));
        const float nm = fmaxf(m, cm);
        const float sc = __expf(m - nm);        // 0 on first chunk (m = -inf)
        const float p  = __expf(e - nm);        // this warp's row probability
        m = nm;
        l = l * sc + p;

        // ---- fold own row into private accumulator (registers only) --------
        acc0.x = acc0.x*sc + p*x0.x;  acc0.y = acc0.y*sc + p*x0.y;
        acc0.z = acc0.z*sc + p*x0.z;  acc0.w = acc0.w*sc + p*x0.w;
        acc1.x = acc1.x*sc + p*x1.x;  acc1.y = acc1.y*sc + p*x1.y;
        acc1.z = acc1.z*sc + p*x1.z;  acc1.w = acc1.w*sc + p*x1.w;
        acc2.x = acc2.x*sc + p*x2.x;  acc2.y = acc2.y*sc + p*x2.y;
        acc2.z = acc2.z*sc + p*x2.z;  acc2.w = acc2.w*sc + p*x2.w;
        acc3.x = acc3.x*sc + p*x3.x;  acc3.y = acc3.y*sc + p*x3.y;
        acc3.z = acc3.z*sc + p*x3.z;  acc3.w = acc3.w*sc + p*x3.w;
    }

    // ---- epilogue: cross-warp reduction of 16 private accumulators ---------
    sacc4[warp * 128 + lane +  0] = acc0;
    sacc4[warp * 128 + lane + 32] = acc1;
    sacc4[warp * 128 + lane + 64] = acc2;
    sacc4[warp * 128 + lane + 96] = acc3;
    if (lane == 0) sl[warp] = l;
    __syncthreads();

    const int bs = b * S_ + s;
    if (tid < D_ / 4) {
        float4 a = make_float4(0.f,0.f,0.f,0.f);
        #pragma unroll
        for (int w = 0; w < CHUNK; w++) {
            float4 t = sacc4[w * 128 + tid];
            a.x += t.x; a.y += t.y; a.z += t.z; a.w += t.w;
        }
        reinterpret_cast<float4*>(g_part_acc + (size_t)bs * D_)[tid] = a;
    }
    if (tid == 0) {
        float L = 0.f;
        #pragma unroll
        for (int w = 0; w < CHUNK; w++) L += sl[w];
        g_part_m[bs] = m;
        g_part_l[bs] = L;
    }
}

// -----------------------------------------------------------------------------
// Pass 2: B*SPLIT2 blocks. Every block redundantly merges the 16 tiny segment
// (m,l) partials; sub-block 0 writes context; each sub-block normalizes its
// 256-token slice of the weights in place.
// -----------------------------------------------------------------------------
__global__ __launch_bounds__(THREADS2)
void attn_pass2(float* __restrict__ context,   // d_out         [B*D]
                float* __restrict__ weights)   // d_out + B*D   [B*T] (raw energies)
{
    __shared__ float sm_[S_];
    __shared__ float sl_[S_];

    const int b   = blockIdx.x / SPLIT2;
    const int s   = blockIdx.x % SPLIT2;
    const int tid = threadIdx.x;

    if (tid < S_) {
        sm_[tid] = g_part_m[b * S_ + tid];
        sl_[tid] = g_part_l[b * S_ + tid];
    }
    __syncthreads();

    float M = neg_inf();
    #pragma unroll
    for (int si = 0; si < S_; si++) M = fmaxf(M, sm_[si]);
    float L = 0.f;
    #pragma unroll
    for (int si = 0; si < S_; si++) L += sl_[si] * __expf(sm_[si] - M);
    const float invL = 1.f / L;

    if (s == 0) {
        // context[b, tid] and [b, tid+256]
        #pragma unroll
        for (int h = 0; h < 2; h++) {
            const int col = tid + h * THREADS2;
            float a = 0.f;
            #pragma unroll
            for (int si = 0; si < S_; si++)
                a += g_part_acc[(size_t)(b * S_ + si) * D_ + col] * __expf(sm_[si] - M);
            context[(size_t)b * D_ + col] = a * invL;
        }
    }

    // normalize this block's 256-token slice
    const int t = s * (T_ / SPLIT2) + tid;
    const size_t idx = (size_t)b * T_ + t;
    weights[idx] = __expf(weights[idx] - M) * invL;
}

// -----------------------------------------------------------------------------
extern "C" void kernel_launch(void* const* d_in, const int* in_sizes, int n_in,
                              void* d_out, int out_size)
{
    const float* x = (const float*)d_in[0];   // encoder_outputs [B,T,D]
    const float* v = (const float*)d_in[1];   // attn_weights_param [D,1]
    float* out = (float*)d_out;
    float* ctx = out;                 // [B*D]
    float* wts = out + B_ * D_;       // [B*T]

    attn_pass1<<<B_ * S_, THREADS>>>(x, v, wts);
    attn_pass2<<<B_ * SPLIT2, THREADS2>>>(ctx, wts);
}